// round 4
// baseline (speedup 1.0000x reference)
#include <cuda_runtime.h>
#include <math.h>

#define NN   268
#define NSP  71824
#define PI_D 3.141592653589793238462643383279502884

static __device__ __align__(16) float g_H0[512 * NSP];
static __device__ __align__(16) float g_H1[512 * NSP];
static __device__ __align__(16) float g_F [512 * NN * 40];      // [bc][x][n] n<20 Re, n>=20 Im
static __device__ __align__(16) float g_Hf[8 * 40 * 64 * 40];   // [b][m][i][n]
static __device__ __align__(16) float g_OF[8 * 40 * 64 * 40];   // [b][m][o][n]
static __device__ __align__(16) float g_G [8 * NN * 64 * 40];   // [b][x][o][n]
static __device__ __align__(16) float g_Q [8 * 256 * 256];
static __device__ __align__(16) float g_Bt  [NN * 40];          // [t][n]
static __device__ __align__(16) float g_Exc [40 * NN];
static __device__ __align__(16) float g_Exs [40 * NN];
static __device__ __align__(16) float g_Ixc [40 * NN];
static __device__ __align__(16) float g_Ixs [40 * NN];
static __device__ __align__(16) float g_Itc [20 * NN];
static __device__ __align__(16) float g_Its [20 * NN];
static __device__ float g_v[72];

__global__ void k_basis() {
    int idx = blockIdx.x * 256 + threadIdx.x;
    const double w = 2.0 * PI_D / 268.0;
    if (idx < 10720) {                       // Bt[t][n]
        int t = idx / 40, n = idx % 40;
        int k = (n < 20) ? n : n - 20;
        double a = w * ((k * t) % 268);
        g_Bt[idx] = (n < 20) ? (float)cos(a) : (float)(-sin(a));
    } else if (idx < 21440) {                // Exc/Exs[m][x]
        int q = idx - 10720;
        int m = q / NN, x = q % NN;
        int kx = (m < 20) ? m : 228 + m;
        double a = w * ((kx * x) % 268);
        g_Exc[q] = (float)cos(a);
        g_Exs[q] = (float)(-sin(a));
    } else if (idx < 32160) {                // Ixc/Ixs[m][x], incl 1/N^2
        int q = idx - 21440;
        int m = q / NN, x = q % NN;
        int kx = (m < 20) ? m : 228 + m;
        double a = w * ((kx * x) % 268);
        double sc = 1.0 / (268.0 * 268.0);
        g_Ixc[q] = (float)(cos(a) * sc);
        g_Ixs[q] = (float)(sin(a) * sc);
    } else if (idx < 37520) {                // Itc/Its[k][t]
        int q = idx - 32160;
        int k = q / NN, t = q % NN;
        double a = w * ((k * t) % 268);
        double f = (k == 0) ? 1.0 : 2.0;
        g_Itc[q] = (float)(f * cos(a));
        g_Its[q] = (float)(f * sin(a));
    }
}

__global__ void k_v(const float* __restrict__ f1w, const float* __restrict__ f1b,
                    const float* __restrict__ f2w, const float* __restrict__ f2b,
                    const float* __restrict__ f3w, const float* __restrict__ f3b) {
    int tid = threadIdx.x;
    if (tid < 64) {
        float acc = 0.f;
        for (int j = 0; j < 32; j++) {
            float s = 0.f;
            for (int r = 0; r < 128; r++) s += f2w[j * 128 + r] * f1w[r * 64 + tid];
            acc += f3w[j] * s;
        }
        g_v[tid] = acc;
    } else if (tid == 64) {
        float acc = f3b[0];
        for (int j = 0; j < 32; j++) {
            float s = f2b[j];
            for (int r = 0; r < 128; r++) s += f2w[j * 128 + r] * f1b[r];
            acc += f3w[j] * s;
        }
        g_v[64] = acc;
    }
}

// Q[b][x][t] = sum_i X[b][i][t]*wiw[x][i] + wib[x]
__global__ __launch_bounds__(256) void k_liftQ(const float* __restrict__ X,
                                               const float* __restrict__ wiw,
                                               const float* __restrict__ wib) {
    int x = blockIdx.x, b = blockIdx.y, t = threadIdx.x;
    float acc = wib[x];
#pragma unroll
    for (int i = 0; i < 8; i++)
        acc += X[((size_t)b * 8 + i) * 256 + t] * wiw[x * 8 + i];
    g_Q[((size_t)b * 256 + x) * 256 + t] = acc;
}

// H0 padded 268x268: Q*w0w[c]+w0b[c] inside, 0 outside
__global__ __launch_bounds__(256) void k_expand(const float* __restrict__ w0w,
                                                const float* __restrict__ w0b) {
    int idx = blockIdx.x * 256 + threadIdx.x;
    if (idx >= 512 * (NSP / 4)) return;
    int p4 = idx % (NSP / 4), bc = idx / (NSP / 4);
    int c = bc & 63, b = bc >> 6;
    int p = p4 * 4, x = p / NN, t0 = p % NN;
    float4 v = make_float4(0.f, 0.f, 0.f, 0.f);
    if (x < 256 && t0 < 256) {
        float4 q = *(const float4*)&g_Q[((size_t)b * 256 + x) * 256 + t0];
        float wv = w0w[c], bb = w0b[c];
        v.x = q.x * wv + bb; v.y = q.y * wv + bb;
        v.z = q.z * wv + bb; v.w = q.w * wv + bb;
    }
    *(float4*)&g_H0[(size_t)bc * NSP + p] = v;
}

// F[bc][x][n] = sum_t H[bc][x][t]*Bt[t][n]
__global__ __launch_bounds__(160) void k_dftt(int sel) {
    const float* __restrict__ H = sel ? g_H1 : g_H0;
    __shared__ float sH[4][NN];
    int bc = blockIdx.y, x0 = blockIdx.x * 4, tid = threadIdx.x;
    const float* src = H + (size_t)bc * NSP + (size_t)x0 * NN;
    for (int idx = tid; idx < 4 * NN; idx += 160) sH[idx / NN][idx % NN] = src[idx];
    __syncthreads();
    int r = tid / 40, n = tid % 40;
    float a = 0.f;
#pragma unroll 4
    for (int t = 0; t < NN; t++) a += sH[r][t] * __ldg(&g_Bt[t * 40 + n]);
    g_F[((size_t)bc * NN + x0 + r) * 40 + n] = a;
}

// Hf[b][m][i][n] from F via 40-mode x-DFT
__global__ __launch_bounds__(800) void k_dftx() {
    __shared__ float sF[NN * 40];
    int bc = blockIdx.x, tid = threadIdx.x;
    const float* src = g_F + (size_t)bc * NN * 40;
    for (int i = tid; i < NN * 40; i += 800) sF[i] = src[i];
    __syncthreads();
    int m = tid / 20, kt = tid % 20;
    float aR = 0.f, aI = 0.f;
    for (int x = 0; x < NN; x++) {
        float c = __ldg(&g_Exc[m * NN + x]), s = __ldg(&g_Exs[m * NN + x]);
        float fr = sF[x * 40 + kt], fi = sF[x * 40 + 20 + kt];
        aR += fr * c - fi * s;
        aI += fr * s + fi * c;
    }
    int b = bc >> 6, i = bc & 63;
    float* dst = g_Hf + (((size_t)b * 40 + m) * 64 + i) * 40;
    dst[kt] = aR; dst[20 + kt] = aI;
}

// OF[b][m][o][kt] = sum_i Hf[b][m][i][kt] * W[l][i][o][mm][kt]  (complex)
__global__ __launch_bounds__(640) void k_mix(int layer,
        const float* __restrict__ w1r, const float* __restrict__ w1i,
        const float* __restrict__ w2r, const float* __restrict__ w2i) {
    __shared__ float sH[2560];
    int m = blockIdx.x, b = blockIdx.y, tid = threadIdx.x;
    const float* src = g_Hf + ((size_t)b * 40 + m) * 2560;
    for (int i = tid; i < 2560; i += 640) sH[i] = src[i];
    __syncthreads();
    int kt = tid % 20, oh = tid / 20;
    const float* wr = (m < 20) ? w1r : w2r;
    const float* wi = (m < 20) ? w1i : w2i;
    int mm = (m < 20) ? m : m - 20;
    float aR0 = 0.f, aI0 = 0.f, aR1 = 0.f, aI1 = 0.f;
    for (int i = 0; i < 64; i++) {
        float hr = sH[i * 40 + kt], hi = sH[i * 40 + 20 + kt];
        size_t o0 = ((((size_t)layer * 64 + i) * 64 + oh) * 20 + mm) * 20 + kt;
        float w0r = __ldg(&wr[o0]),          w0i = __ldg(&wi[o0]);
        float w1rv = __ldg(&wr[o0 + 12800]), w1iv = __ldg(&wi[o0 + 12800]);
        aR0 += hr * w0r - hi * w0i;   aI0 += hr * w0i + hi * w0r;
        aR1 += hr * w1rv - hi * w1iv; aI1 += hr * w1iv + hi * w1rv;
    }
    float* d0 = g_OF + (((size_t)b * 40 + m) * 64 + oh) * 40;
    d0[kt] = aR0; d0[20 + kt] = aI0;
    d0[32 * 40 + kt] = aR1; d0[32 * 40 + 20 + kt] = aI1;
}

// G[b][x][o][n] = inverse x-DFT of OF
__global__ __launch_bounds__(268) void k_invx() {
    __shared__ float sOF[1600];
    int o = blockIdx.x, b = blockIdx.y, tid = threadIdx.x;
    for (int idx = tid; idx < 1600; idx += 268)
        sOF[idx] = g_OF[(((size_t)b * 40 + idx / 40) * 64 + o) * 40 + idx % 40];
    __syncthreads();
    int x = tid;
    float Gr[20] = {}, Gi[20] = {};
    for (int m = 0; m < 40; m++) {
        float c = __ldg(&g_Ixc[m * NN + x]), s = __ldg(&g_Ixs[m * NN + x]);
#pragma unroll
        for (int kt = 0; kt < 20; kt++) {
            float orv = sOF[m * 40 + kt], oiv = sOF[m * 40 + 20 + kt];
            Gr[kt] += orv * c - oiv * s;
            Gi[kt] += orv * s + oiv * c;
        }
    }
    float* dst = g_G + (((size_t)b * NN + x) * 64 + o) * 40;
#pragma unroll
    for (int kt = 0; kt < 20; kt++) { dst[kt] = Gr[kt]; dst[20 + kt] = Gi[kt]; }
}

// inv t-DFT + 1x1 conv + bias + exact GELU, per (b,x)
__global__ __launch_bounds__(512) void k_convinv(int sel, int layer,
                                                 const float* __restrict__ cw,
                                                 const float* __restrict__ cb) {
    extern __shared__ float sm[];
    float* sH   = sm;                 // [64][268]
    float* sCW  = sH + 64 * NN;       // [64o][64i]
    float* sG   = sCW + 4096;         // [64][40]
    float* sItc = sG + 2560;          // [20][268]
    float* sIts = sItc + 20 * NN;     // [20][268]
    const float* __restrict__ H  = sel ? g_H1 : g_H0;
    float* __restrict__       Hn = sel ? g_H0 : g_H1;
    int x = blockIdx.x, b = blockIdx.y, tid = threadIdx.x;
    for (int idx = tid; idx < 64 * NN; idx += 512)
        sH[idx] = H[(((size_t)b * 64 + idx / NN) * NN + x) * NN + idx % NN];
    for (int idx = tid; idx < 4096; idx += 512)
        sCW[idx] = cw[layer * 4096 + idx];
    for (int idx = tid; idx < 2560; idx += 512)
        sG[idx] = g_G[((size_t)b * NN + x) * 2560 + idx];
    for (int idx = tid; idx < 20 * NN; idx += 512) {
        sItc[idx] = g_Itc[idx];
        sIts[idx] = g_Its[idx];
    }
    __syncthreads();
    for (int q = tid; q < 64 * 67; q += 512) {
        int o = q / 67, t0 = (q % 67) * 4;
        float4 acc = make_float4(0.f, 0.f, 0.f, 0.f);
#pragma unroll 4
        for (int i = 0; i < 64; i++) {
            float w = sCW[o * 64 + i];
            float4 h4 = *(const float4*)&sH[i * NN + t0];
            acc.x += w * h4.x; acc.y += w * h4.y;
            acc.z += w * h4.z; acc.w += w * h4.w;
        }
#pragma unroll
        for (int kt = 0; kt < 20; kt++) {
            float gr = sG[o * 40 + kt], gi = sG[o * 40 + 20 + kt];
            float4 c4 = *(const float4*)&sItc[kt * NN + t0];
            float4 s4 = *(const float4*)&sIts[kt * NN + t0];
            acc.x += gr * c4.x - gi * s4.x;
            acc.y += gr * c4.y - gi * s4.y;
            acc.z += gr * c4.z - gi * s4.z;
            acc.w += gr * c4.w - gi * s4.w;
        }
        float cbv = __ldg(&cb[layer * 64 + o]);
        float4 out;
        float v;
        v = acc.x + cbv; out.x = 0.5f * v * (1.f + erff(v * 0.7071067811865475f));
        v = acc.y + cbv; out.y = 0.5f * v * (1.f + erff(v * 0.7071067811865475f));
        v = acc.z + cbv; out.z = 0.5f * v * (1.f + erff(v * 0.7071067811865475f));
        v = acc.w + cbv; out.w = 0.5f * v * (1.f + erff(v * 0.7071067811865475f));
        *(float4*)&Hn[(((size_t)b * 64 + o) * NN + x) * NN + t0] = out;
    }
}

__global__ __launch_bounds__(256) void k_head(int sel, float* __restrict__ out) {
    const float* __restrict__ H = sel ? g_H1 : g_H0;
    __shared__ float sv[72];
    int tid = threadIdx.x;
    if (tid < 65) sv[tid] = g_v[tid];
    __syncthreads();
    int x = blockIdx.x, b = blockIdx.y;
    const float* base = H + ((size_t)b * 64 * NN + x) * NN + tid;
    float acc = sv[64];
#pragma unroll 8
    for (int c = 0; c < 64; c++) acc += base[(size_t)c * NSP] * sv[c];
    out[((size_t)b * 256 + x) * 256 + tid] = acc;
}

extern "C" void kernel_launch(void* const* d_in, const int* in_sizes, int n_in,
                              void* d_out, int out_size) {
    (void)in_sizes; (void)n_in; (void)out_size;
    const float* x    = (const float*)d_in[0];
    const float* wi_w = (const float*)d_in[1];
    const float* wi_b = (const float*)d_in[2];
    const float* w0_w = (const float*)d_in[3];
    const float* w0_b = (const float*)d_in[4];
    const float* sw1r = (const float*)d_in[5];
    const float* sw1i = (const float*)d_in[6];
    const float* sw2r = (const float*)d_in[7];
    const float* sw2i = (const float*)d_in[8];
    const float* cw   = (const float*)d_in[9];
    const float* cb   = (const float*)d_in[10];

    const int SM_CONV = (64 * NN + 4096 + 2560 + 40 * NN) * 4;  // 138112
    cudaFuncSetAttribute(k_convinv, cudaFuncAttributeMaxDynamicSharedMemorySize, SM_CONV);

    k_basis<<<147, 256>>>();
    k_v<<<1, 96>>>((const float*)d_in[11], (const float*)d_in[12],
                   (const float*)d_in[13], (const float*)d_in[14],
                   (const float*)d_in[15], (const float*)d_in[16]);
    k_liftQ<<<dim3(256, 8), 256>>>(x, wi_w, wi_b);
    k_expand<<<(512 * (NSP / 4) + 255) / 256, 256>>>(w0_w, w0_b);

    int sel = 0;
    for (int l = 0; l < 4; l++) {
        k_dftt<<<dim3(67, 512), 160>>>(sel);
        k_dftx<<<512, 800>>>();
        k_mix<<<dim3(40, 8), 640>>>(l, sw1r, sw1i, sw2r, sw2i);
        k_invx<<<dim3(64, 8), 268>>>();
        k_convinv<<<dim3(NN, 8), 512, SM_CONV>>>(sel, l, cw, cb);
        sel ^= 1;
    }
    k_head<<<dim3(256, 8), 256>>>(sel, (float*)d_out);
}

// round 5
// speedup vs baseline: 1.4391x; 1.4391x over previous
#include <cuda_runtime.h>
#include <math.h>

#define NN   268
#define NSP  71824
#define PI_D 3.141592653589793238462643383279502884

static __device__ __align__(16) float g_H0[512 * NSP];
static __device__ __align__(16) float g_H1[512 * NSP];
static __device__ __align__(16) float g_F [512 * NN * 40];      // [bc][x][n] n<20 Re, n>=20 Im
static __device__ __align__(16) float g_Hf[8 * 40 * 64 * 40];   // [b][m][i][n]
static __device__ __align__(16) float g_OF[8 * 40 * 64 * 40];   // [b][m][o][n]
static __device__ __align__(16) float g_G [8 * NN * 64 * 40];   // [b][x][o][n]
static __device__ __align__(16) float g_Q [8 * 256 * 256];
static __device__ __align__(16) float g_Bt  [NN * 40];          // [t][n] (n as 10 float4)
static __device__ __align__(16) float g_Exc [40 * NN];
static __device__ __align__(16) float g_Exs [40 * NN];
static __device__ __align__(16) float g_Ixc [40 * NN];
static __device__ __align__(16) float g_Ixs [40 * NN];
static __device__ __align__(16) float g_Itc [20 * NN];
static __device__ __align__(16) float g_Its [20 * NN];
static __device__ __align__(16) float g_cwT[4 * 64 * 64];       // [l][i][o]
static __device__ float g_v[72];

__global__ void k_basis() {
    int idx = blockIdx.x * 256 + threadIdx.x;
    const double w = 2.0 * PI_D / 268.0;
    if (idx < 10720) {                       // Bt[t][n]
        int t = idx / 40, n = idx % 40;
        int k = (n < 20) ? n : n - 20;
        double a = w * ((k * t) % 268);
        g_Bt[idx] = (n < 20) ? (float)cos(a) : (float)(-sin(a));
    } else if (idx < 21440) {                // Exc/Exs[m][x]
        int q = idx - 10720;
        int m = q / NN, x = q % NN;
        int kx = (m < 20) ? m : 228 + m;
        double a = w * ((kx * x) % 268);
        g_Exc[q] = (float)cos(a);
        g_Exs[q] = (float)(-sin(a));
    } else if (idx < 32160) {                // Ixc/Ixs[m][x], incl 1/N^2
        int q = idx - 21440;
        int m = q / NN, x = q % NN;
        int kx = (m < 20) ? m : 228 + m;
        double a = w * ((kx * x) % 268);
        double sc = 1.0 / (268.0 * 268.0);
        g_Ixc[q] = (float)(cos(a) * sc);
        g_Ixs[q] = (float)(sin(a) * sc);
    } else if (idx < 37520) {                // Itc/Its[k][t]
        int q = idx - 32160;
        int k = q / NN, t = q % NN;
        double a = w * ((k * t) % 268);
        double f = (k == 0) ? 1.0 : 2.0;
        g_Itc[q] = (float)(f * cos(a));
        g_Its[q] = (float)(f * sin(a));
    }
}

__global__ void k_cwT(const float* __restrict__ cw) {
    int idx = blockIdx.x * 256 + threadIdx.x;
    if (idx < 16384) {
        int l = idx >> 12, r = idx & 4095, i = r >> 6, o = r & 63;
        g_cwT[idx] = cw[(l << 12) + (o << 6) + i];
    }
}

__global__ void k_v(const float* __restrict__ f1w, const float* __restrict__ f1b,
                    const float* __restrict__ f2w, const float* __restrict__ f2b,
                    const float* __restrict__ f3w, const float* __restrict__ f3b) {
    int tid = threadIdx.x;
    if (tid < 64) {
        float acc = 0.f;
        for (int j = 0; j < 32; j++) {
            float s = 0.f;
            for (int r = 0; r < 128; r++) s += f2w[j * 128 + r] * f1w[r * 64 + tid];
            acc += f3w[j] * s;
        }
        g_v[tid] = acc;
    } else if (tid == 64) {
        float acc = f3b[0];
        for (int j = 0; j < 32; j++) {
            float s = f2b[j];
            for (int r = 0; r < 128; r++) s += f2w[j * 128 + r] * f1b[r];
            acc += f3w[j] * s;
        }
        g_v[64] = acc;
    }
}

// Q[b][x][t] = sum_i X[b][i][t]*wiw[x][i] + wib[x]
__global__ __launch_bounds__(256) void k_liftQ(const float* __restrict__ X,
                                               const float* __restrict__ wiw,
                                               const float* __restrict__ wib) {
    int x = blockIdx.x, b = blockIdx.y, t = threadIdx.x;
    float acc = wib[x];
#pragma unroll
    for (int i = 0; i < 8; i++)
        acc += X[((size_t)b * 8 + i) * 256 + t] * wiw[x * 8 + i];
    g_Q[((size_t)b * 256 + x) * 256 + t] = acc;
}

// H0 padded 268x268: Q*w0w[c]+w0b[c] inside, 0 outside
__global__ __launch_bounds__(256) void k_expand(const float* __restrict__ w0w,
                                                const float* __restrict__ w0b) {
    int idx = blockIdx.x * 256 + threadIdx.x;
    if (idx >= 512 * (NSP / 4)) return;
    int p4 = idx % (NSP / 4), bc = idx / (NSP / 4);
    int c = bc & 63, b = bc >> 6;
    int p = p4 * 4, x = p / NN, t0 = p % NN;
    float4 v = make_float4(0.f, 0.f, 0.f, 0.f);
    if (x < 256 && t0 < 256) {
        float4 q = *(const float4*)&g_Q[((size_t)b * 256 + x) * 256 + t0];
        float wv = w0w[c], bb = w0b[c];
        v.x = q.x * wv + bb; v.y = q.y * wv + bb;
        v.z = q.z * wv + bb; v.w = q.w * wv + bb;
    }
    *(float4*)&g_H0[(size_t)bc * NSP + p] = v;
}

// F[bc][x][n] = sum_t H[bc][x][t]*Bt[t][n]   (thread = 1 row x 4 modes)
__global__ __launch_bounds__(160) void k_dftt(int sel) {
    const float* __restrict__ H = sel ? g_H1 : g_H0;
    __shared__ float sH[16][NN];
    int bc = blockIdx.y, x0 = blockIdx.x * 16, tid = threadIdx.x;
    for (int idx = tid; idx < 16 * NN; idx += 160) {
        int r = idx / NN, t = idx % NN;
        int x = x0 + r;
        sH[r][t] = (x < NN) ? H[(size_t)bc * NSP + (size_t)x * NN + t] : 0.f;
    }
    __syncthreads();
    int tx = tid % 10, ty = tid / 10;
    int x = x0 + ty;
    if (x >= NN) return;
    const float4* Bt4 = reinterpret_cast<const float4*>(g_Bt);
    float4 acc = make_float4(0.f, 0.f, 0.f, 0.f);
#pragma unroll 4
    for (int t = 0; t < NN; t++) {
        float4 b4 = __ldg(&Bt4[t * 10 + tx]);
        float h = sH[ty][t];
        acc.x += h * b4.x; acc.y += h * b4.y;
        acc.z += h * b4.z; acc.w += h * b4.w;
    }
    *(float4*)&g_F[((size_t)bc * NN + x) * 40 + tx * 4] = acc;
}

// Hf[b][m][i][n] from F via 40-mode x-DFT
__global__ __launch_bounds__(800) void k_dftx() {
    __shared__ float sF[NN * 40];
    int bc = blockIdx.x, tid = threadIdx.x;
    const float* src = g_F + (size_t)bc * NN * 40;
    for (int i = tid; i < NN * 40; i += 800) sF[i] = src[i];
    __syncthreads();
    int m = tid / 20, kt = tid % 20;
    float aR = 0.f, aI = 0.f;
    for (int x = 0; x < NN; x++) {
        float c = __ldg(&g_Exc[m * NN + x]), s = __ldg(&g_Exs[m * NN + x]);
        float fr = sF[x * 40 + kt], fi = sF[x * 40 + 20 + kt];
        aR += fr * c - fi * s;
        aI += fr * s + fi * c;
    }
    int b = bc >> 6, i = bc & 63;
    float* dst = g_Hf + (((size_t)b * 40 + m) * 64 + i) * 40;
    dst[kt] = aR; dst[20 + kt] = aI;
}

// OF[b][m][o][kt] = sum_i Hf[b][m][i][kt] * W[l][i][o][mm][kt]  (complex)
__global__ __launch_bounds__(640) void k_mix(int layer,
        const float* __restrict__ w1r, const float* __restrict__ w1i,
        const float* __restrict__ w2r, const float* __restrict__ w2i) {
    __shared__ float sH[2560];
    int m = blockIdx.x, b = blockIdx.y, tid = threadIdx.x;
    const float* src = g_Hf + ((size_t)b * 40 + m) * 2560;
    for (int i = tid; i < 2560; i += 640) sH[i] = src[i];
    __syncthreads();
    int kt = tid % 20, oh = tid / 20;
    const float* wr = (m < 20) ? w1r : w2r;
    const float* wi = (m < 20) ? w1i : w2i;
    int mm = (m < 20) ? m : m - 20;
    float aR0 = 0.f, aI0 = 0.f, aR1 = 0.f, aI1 = 0.f;
    for (int i = 0; i < 64; i++) {
        float hr = sH[i * 40 + kt], hi = sH[i * 40 + 20 + kt];
        size_t o0 = ((((size_t)layer * 64 + i) * 64 + oh) * 20 + mm) * 20 + kt;
        float w0r = __ldg(&wr[o0]),          w0i = __ldg(&wi[o0]);
        float w1rv = __ldg(&wr[o0 + 12800]), w1iv = __ldg(&wi[o0 + 12800]);
        aR0 += hr * w0r - hi * w0i;   aI0 += hr * w0i + hi * w0r;
        aR1 += hr * w1rv - hi * w1iv; aI1 += hr * w1iv + hi * w1rv;
    }
    float* d0 = g_OF + (((size_t)b * 40 + m) * 64 + oh) * 40;
    d0[kt] = aR0; d0[20 + kt] = aI0;
    d0[32 * 40 + kt] = aR1; d0[32 * 40 + 20 + kt] = aI1;
}

// G[b][x][o][n] = inverse x-DFT of OF
__global__ __launch_bounds__(268) void k_invx() {
    __shared__ float sOF[1600];
    int o = blockIdx.x, b = blockIdx.y, tid = threadIdx.x;
    for (int idx = tid; idx < 1600; idx += 268)
        sOF[idx] = g_OF[(((size_t)b * 40 + idx / 40) * 64 + o) * 40 + idx % 40];
    __syncthreads();
    int x = tid;
    float Gr[20] = {}, Gi[20] = {};
    for (int m = 0; m < 40; m++) {
        float c = __ldg(&g_Ixc[m * NN + x]), s = __ldg(&g_Ixs[m * NN + x]);
#pragma unroll
        for (int kt = 0; kt < 20; kt++) {
            float orv = sOF[m * 40 + kt], oiv = sOF[m * 40 + 20 + kt];
            Gr[kt] += orv * c - oiv * s;
            Gi[kt] += orv * s + oiv * c;
        }
    }
    float* dst = g_G + (((size_t)b * NN + x) * 64 + o) * 40;
#pragma unroll
    for (int kt = 0; kt < 20; kt++) { dst[kt] = Gr[kt]; dst[20 + kt] = Gi[kt]; }
}

// inv t-DFT + 1x1 conv + bias + exact GELU, per (b,x). 8o x 4t register tile.
__global__ __launch_bounds__(544) void k_convinv(int sel, int layer,
                                                 const float* __restrict__ cb) {
    extern __shared__ float sm[];
    float* sH   = sm;                 // [64][268]
    float* sCWT = sH + 64 * NN;       // [64i][64o]
    float* sGT  = sCWT + 4096;        // [40n][68]  (stride 68 pad)
    float* sItc = sGT + 40 * 68;      // [20][268]
    float* sIts = sItc + 20 * NN;     // [20][268]
    const float* __restrict__ H  = sel ? g_H1 : g_H0;
    float* __restrict__       Hn = sel ? g_H0 : g_H1;
    int x = blockIdx.x, b = blockIdx.y, tid = threadIdx.x;
    for (int idx = tid; idx < 64 * NN; idx += 544)
        sH[idx] = H[(((size_t)b * 64 + idx / NN) * NN + x) * NN + idx % NN];
    for (int idx = tid; idx < 4096; idx += 544)
        sCWT[idx] = g_cwT[layer * 4096 + idx];
    for (int idx = tid; idx < 2560; idx += 544) {
        int o = idx / 40, n = idx % 40;
        sGT[n * 68 + o] = g_G[((size_t)b * NN + x) * 2560 + idx];
    }
    for (int idx = tid; idx < 20 * NN; idx += 544) {
        sItc[idx] = g_Itc[idx];
        sIts[idx] = g_Its[idx];
    }
    __syncthreads();
    if (tid >= 536) return;
    int og = tid / 67, tq = tid % 67;
    int o0 = og * 8, t0 = tq * 4;
    float acc[8][4] = {};
#pragma unroll 2
    for (int i = 0; i < 64; i++) {
        float4 h4 = *(const float4*)&sH[i * NN + t0];
        float4 wa = *(const float4*)&sCWT[i * 64 + o0];
        float4 wb = *(const float4*)&sCWT[i * 64 + o0 + 4];
        float w[8] = {wa.x, wa.y, wa.z, wa.w, wb.x, wb.y, wb.z, wb.w};
        float h[4] = {h4.x, h4.y, h4.z, h4.w};
#pragma unroll
        for (int a = 0; a < 8; a++)
#pragma unroll
            for (int c = 0; c < 4; c++) acc[a][c] += w[a] * h[c];
    }
#pragma unroll
    for (int kt = 0; kt < 20; kt++) {
        float4 c4 = *(const float4*)&sItc[kt * NN + t0];
        float4 s4 = *(const float4*)&sIts[kt * NN + t0];
        float4 ga = *(const float4*)&sGT[kt * 68 + o0];
        float4 gb = *(const float4*)&sGT[kt * 68 + o0 + 4];
        float4 ia = *(const float4*)&sGT[(20 + kt) * 68 + o0];
        float4 ib = *(const float4*)&sGT[(20 + kt) * 68 + o0 + 4];
        float gr[8] = {ga.x, ga.y, ga.z, ga.w, gb.x, gb.y, gb.z, gb.w};
        float gi[8] = {ia.x, ia.y, ia.z, ia.w, ib.x, ib.y, ib.z, ib.w};
        float cc[4] = {c4.x, c4.y, c4.z, c4.w};
        float ss[4] = {s4.x, s4.y, s4.z, s4.w};
#pragma unroll
        for (int a = 0; a < 8; a++)
#pragma unroll
            for (int c = 0; c < 4; c++)
                acc[a][c] += gr[a] * cc[c] - gi[a] * ss[c];
    }
#pragma unroll
    for (int a = 0; a < 8; a++) {
        int o = o0 + a;
        float cbv = __ldg(&cb[layer * 64 + o]);
        float4 out;
        float v;
        v = acc[a][0] + cbv; out.x = 0.5f * v * (1.f + erff(v * 0.7071067811865475f));
        v = acc[a][1] + cbv; out.y = 0.5f * v * (1.f + erff(v * 0.7071067811865475f));
        v = acc[a][2] + cbv; out.z = 0.5f * v * (1.f + erff(v * 0.7071067811865475f));
        v = acc[a][3] + cbv; out.w = 0.5f * v * (1.f + erff(v * 0.7071067811865475f));
        *(float4*)&Hn[(((size_t)b * 64 + o) * NN + x) * NN + t0] = out;
    }
}

__global__ __launch_bounds__(256) void k_head(int sel, float* __restrict__ out) {
    const float* __restrict__ H = sel ? g_H1 : g_H0;
    __shared__ float sv[72];
    int tid = threadIdx.x;
    if (tid < 65) sv[tid] = g_v[tid];
    __syncthreads();
    int x = blockIdx.x, b = blockIdx.y;
    const float* base = H + ((size_t)b * 64 * NN + x) * NN + tid;
    float acc = sv[64];
#pragma unroll 8
    for (int c = 0; c < 64; c++) acc += base[(size_t)c * NSP] * sv[c];
    out[((size_t)b * 256 + x) * 256 + tid] = acc;
}

extern "C" void kernel_launch(void* const* d_in, const int* in_sizes, int n_in,
                              void* d_out, int out_size) {
    (void)in_sizes; (void)n_in; (void)out_size;
    const float* x    = (const float*)d_in[0];
    const float* wi_w = (const float*)d_in[1];
    const float* wi_b = (const float*)d_in[2];
    const float* w0_w = (const float*)d_in[3];
    const float* w0_b = (const float*)d_in[4];
    const float* sw1r = (const float*)d_in[5];
    const float* sw1i = (const float*)d_in[6];
    const float* sw2r = (const float*)d_in[7];
    const float* sw2i = (const float*)d_in[8];
    const float* cw   = (const float*)d_in[9];
    const float* cb   = (const float*)d_in[10];

    const int SM_CONV = (64 * NN + 4096 + 40 * 68 + 2 * 20 * NN) * 4;  // 138752
    cudaFuncSetAttribute(k_convinv, cudaFuncAttributeMaxDynamicSharedMemorySize, SM_CONV);

    k_basis<<<147, 256>>>();
    k_cwT<<<64, 256>>>(cw);
    k_v<<<1, 96>>>((const float*)d_in[11], (const float*)d_in[12],
                   (const float*)d_in[13], (const float*)d_in[14],
                   (const float*)d_in[15], (const float*)d_in[16]);
    k_liftQ<<<dim3(256, 8), 256>>>(x, wi_w, wi_b);
    k_expand<<<(512 * (NSP / 4) + 255) / 256, 256>>>(w0_w, w0_b);

    int sel = 0;
    for (int l = 0; l < 4; l++) {
        k_dftt<<<dim3(17, 512), 160>>>(sel);
        k_dftx<<<512, 800>>>();
        k_mix<<<dim3(40, 8), 640>>>(l, sw1r, sw1i, sw2r, sw2i);
        k_invx<<<dim3(64, 8), 268>>>();
        k_convinv<<<dim3(NN, 8), 544, SM_CONV>>>(sel, l, cb);
        sel ^= 1;
    }
    k_head<<<dim3(256, 8), 256>>>(sel, (float*)d_out);
}

// round 6
// speedup vs baseline: 1.4544x; 1.0107x over previous
#include <cuda_runtime.h>
#include <math.h>

#define NN   268
#define NSP  71824
#define PI_D 3.141592653589793238462643383279502884

typedef unsigned long long ull;

static __device__ __align__(16) float g_H0[512 * NSP];
static __device__ __align__(16) float g_H1[512 * NSP];
static __device__ __align__(16) float g_F [512 * NN * 40];      // [bc][x][n] n<20 Re, n>=20 Im
static __device__ __align__(16) float g_Hf[8 * 40 * 64 * 40];   // [b][m][i][n]
static __device__ __align__(16) float g_OF[8 * 40 * 64 * 40];   // [b][m][o][n]
static __device__ __align__(16) float g_G [8 * NN * 64 * 40];   // [b][x][o][n]
static __device__ __align__(16) float g_Q [8 * 256 * 256];
static __device__ __align__(16) float g_Bt  [NN * 40];          // [t][n]
static __device__ __align__(16) float g_Exc [40 * NN];
static __device__ __align__(16) float g_Exs [40 * NN];
static __device__ __align__(16) float g_Ixc [40 * NN];
static __device__ __align__(16) float g_Ixs [40 * NN];
static __device__ __align__(16) float g_Itc [20 * NN];
static __device__ __align__(16) float g_Its [20 * NN];
static __device__ __align__(16) float g_cwT[4 * 64 * 64];       // [l][i][o]
static __device__ float g_v[72];

__device__ __forceinline__ ull pk2(float lo, float hi) {
    ull r; asm("mov.b64 %0, {%1,%2};" : "=l"(r) : "f"(lo), "f"(hi)); return r;
}
__device__ __forceinline__ void fma2(ull& d, ull a, ull b) {
    asm("fma.rn.f32x2 %0, %1, %2, %3;" : "=l"(d) : "l"(a), "l"(b), "l"(d));
}
__device__ __forceinline__ float2 up2(ull v) {
    float2 r; asm("mov.b64 {%0,%1}, %2;" : "=f"(r.x), "=f"(r.y) : "l"(v)); return r;
}

// merged setup: basis tables + cw transpose + collapsed fc head vector
__global__ void k_setup(const float* __restrict__ cw,
                        const float* __restrict__ f1w, const float* __restrict__ f1b,
                        const float* __restrict__ f2w, const float* __restrict__ f2b,
                        const float* __restrict__ f3w, const float* __restrict__ f3b) {
    int blk = blockIdx.x, tid = threadIdx.x;
    const double w = 2.0 * PI_D / 268.0;
    if (blk < 147) {
        int idx = blk * 256 + tid;
        if (idx < 10720) {                       // Bt[t][n]
            int t = idx / 40, n = idx % 40;
            int k = (n < 20) ? n : n - 20;
            double a = w * ((k * t) % 268);
            g_Bt[idx] = (n < 20) ? (float)cos(a) : (float)(-sin(a));
        } else if (idx < 21440) {                // Exc/Exs[m][x]
            int q = idx - 10720;
            int m = q / NN, x = q % NN;
            int kx = (m < 20) ? m : 228 + m;
            double a = w * ((kx * x) % 268);
            g_Exc[q] = (float)cos(a);
            g_Exs[q] = (float)(-sin(a));
        } else if (idx < 32160) {                // Ixc/Ixs[m][x], incl 1/N^2
            int q = idx - 21440;
            int m = q / NN, x = q % NN;
            int kx = (m < 20) ? m : 228 + m;
            double a = w * ((kx * x) % 268);
            double sc = 1.0 / (268.0 * 268.0);
            g_Ixc[q] = (float)(cos(a) * sc);
            g_Ixs[q] = (float)(sin(a) * sc);
        } else if (idx < 37520) {                // Itc/Its[k][t]
            int q = idx - 32160;
            int k = q / NN, t = q % NN;
            double a = w * ((k * t) % 268);
            double f = (k == 0) ? 1.0 : 2.0;
            g_Itc[q] = (float)(f * cos(a));
            g_Its[q] = (float)(f * sin(a));
        }
    } else if (blk < 211) {                      // cw transpose
        int idx = (blk - 147) * 256 + tid;
        if (idx < 16384) {
            int l = idx >> 12, r = idx & 4095, i = r >> 6, o = r & 63;
            g_cwT[idx] = cw[(l << 12) + (o << 6) + i];
        }
    } else {                                     // collapsed fc head
        if (tid < 64) {
            float acc = 0.f;
            for (int j = 0; j < 32; j++) {
                float s = 0.f;
                for (int r = 0; r < 128; r++) s += f2w[j * 128 + r] * f1w[r * 64 + tid];
                acc += f3w[j] * s;
            }
            g_v[tid] = acc;
        } else if (tid == 64) {
            float acc = f3b[0];
            for (int j = 0; j < 32; j++) {
                float s = f2b[j];
                for (int r = 0; r < 128; r++) s += f2w[j * 128 + r] * f1b[r];
                acc += f3w[j] * s;
            }
            g_v[64] = acc;
        }
    }
}

// Q[b][x][t] = sum_i X[b][i][t]*wiw[x][i] + wib[x]
__global__ __launch_bounds__(256) void k_liftQ(const float* __restrict__ X,
                                               const float* __restrict__ wiw,
                                               const float* __restrict__ wib) {
    int x = blockIdx.x, b = blockIdx.y, t = threadIdx.x;
    float acc = wib[x];
#pragma unroll
    for (int i = 0; i < 8; i++)
        acc += X[((size_t)b * 8 + i) * 256 + t] * wiw[x * 8 + i];
    g_Q[((size_t)b * 256 + x) * 256 + t] = acc;
}

// H0 padded 268x268: Q*w0w[c]+w0b[c] inside, 0 outside
__global__ __launch_bounds__(256) void k_expand(const float* __restrict__ w0w,
                                                const float* __restrict__ w0b) {
    int idx = blockIdx.x * 256 + threadIdx.x;
    if (idx >= 512 * (NSP / 4)) return;
    int p4 = idx % (NSP / 4), bc = idx / (NSP / 4);
    int c = bc & 63, b = bc >> 6;
    int p = p4 * 4, x = p / NN, t0 = p % NN;
    float4 v = make_float4(0.f, 0.f, 0.f, 0.f);
    if (x < 256 && t0 < 256) {
        float4 q = *(const float4*)&g_Q[((size_t)b * 256 + x) * 256 + t0];
        float wv = w0w[c], bb = w0b[c];
        v.x = q.x * wv + bb; v.y = q.y * wv + bb;
        v.z = q.z * wv + bb; v.w = q.w * wv + bb;
    }
    *(float4*)&g_H0[(size_t)bc * NSP + p] = v;
}

// F[bc][x][n] = sum_t H[bc][x][t]*Bt[t][n]   (thread = 1 row x 4 modes, f32x2)
__global__ __launch_bounds__(160) void k_dftt(int sel) {
    const float* __restrict__ H = sel ? g_H1 : g_H0;
    __shared__ float sH[16][NN];
    int bc = blockIdx.y, x0 = blockIdx.x * 16, tid = threadIdx.x;
    for (int idx = tid; idx < 16 * NN; idx += 160) {
        int r = idx / NN, t = idx % NN;
        int x = x0 + r;
        sH[r][t] = (x < NN) ? H[(size_t)bc * NSP + (size_t)x * NN + t] : 0.f;
    }
    __syncthreads();
    int tx = tid % 10, ty = tid / 10;
    int x = x0 + ty;
    if (x >= NN) return;
    ull a01 = 0ULL, a23 = 0ULL;
#pragma unroll 4
    for (int t = 0; t < NN; t++) {
        const ull* b2 = reinterpret_cast<const ull*>(&g_Bt[t * 40 + tx * 4]);
        ull hp = pk2(sH[ty][t], sH[ty][t]);
        fma2(a01, __ldg(&b2[0]), hp);
        fma2(a23, __ldg(&b2[1]), hp);
    }
    float2 lo = up2(a01), hi = up2(a23);
    *(float4*)&g_F[((size_t)bc * NN + x) * 40 + tx * 4] =
        make_float4(lo.x, lo.y, hi.x, hi.y);
}

// Hf[b][m][i][n] from F via 40-mode x-DFT
__global__ __launch_bounds__(800) void k_dftx() {
    __shared__ float sF[NN * 40];
    int bc = blockIdx.x, tid = threadIdx.x;
    const float* src = g_F + (size_t)bc * NN * 40;
    for (int i = tid; i < NN * 40; i += 800) sF[i] = src[i];
    __syncthreads();
    int m = tid / 20, kt = tid % 20;
    float aR = 0.f, aI = 0.f;
    for (int x = 0; x < NN; x++) {
        float c = __ldg(&g_Exc[m * NN + x]), s = __ldg(&g_Exs[m * NN + x]);
        float fr = sF[x * 40 + kt], fi = sF[x * 40 + 20 + kt];
        aR += fr * c - fi * s;
        aI += fr * s + fi * c;
    }
    int b = bc >> 6, i = bc & 63;
    float* dst = g_Hf + (((size_t)b * 40 + m) * 64 + i) * 40;
    dst[kt] = aR; dst[20 + kt] = aI;
}

// OF[b][m][o][kt] = sum_i Hf[b][m][i][kt] * W[l][i][o][mm][kt]  (complex)
__global__ __launch_bounds__(640) void k_mix(int layer,
        const float* __restrict__ w1r, const float* __restrict__ w1i,
        const float* __restrict__ w2r, const float* __restrict__ w2i) {
    __shared__ float sH[2560];
    int m = blockIdx.x, b = blockIdx.y, tid = threadIdx.x;
    const float* src = g_Hf + ((size_t)b * 40 + m) * 2560;
    for (int i = tid; i < 2560; i += 640) sH[i] = src[i];
    __syncthreads();
    int kt = tid % 20, oh = tid / 20;
    const float* wr = (m < 20) ? w1r : w2r;
    const float* wi = (m < 20) ? w1i : w2i;
    int mm = (m < 20) ? m : m - 20;
    float aR0 = 0.f, aI0 = 0.f, aR1 = 0.f, aI1 = 0.f;
    for (int i = 0; i < 64; i++) {
        float hr = sH[i * 40 + kt], hi = sH[i * 40 + 20 + kt];
        size_t o0 = ((((size_t)layer * 64 + i) * 64 + oh) * 20 + mm) * 20 + kt;
        float w0r = __ldg(&wr[o0]),          w0i = __ldg(&wi[o0]);
        float w1rv = __ldg(&wr[o0 + 12800]), w1iv = __ldg(&wi[o0 + 12800]);
        aR0 += hr * w0r - hi * w0i;   aI0 += hr * w0i + hi * w0r;
        aR1 += hr * w1rv - hi * w1iv; aI1 += hr * w1iv + hi * w1rv;
    }
    float* d0 = g_OF + (((size_t)b * 40 + m) * 64 + oh) * 40;
    d0[kt] = aR0; d0[20 + kt] = aI0;
    d0[32 * 40 + kt] = aR1; d0[32 * 40 + 20 + kt] = aI1;
}

// G[b][x][o][n] = inverse x-DFT of OF  (f32x2, pairs over kt)
__global__ __launch_bounds__(268) void k_invx() {
    __shared__ float sOF[1600];
    int o = blockIdx.x, b = blockIdx.y, tid = threadIdx.x;
    for (int idx = tid; idx < 1600; idx += 268)
        sOF[idx] = g_OF[(((size_t)b * 40 + idx / 40) * 64 + o) * 40 + idx % 40];
    __syncthreads();
    int x = tid;
    ull Gr[10] = {}, Gi[10] = {};
    for (int m = 0; m < 40; m++) {
        float c = __ldg(&g_Ixc[m * NN + x]), s = __ldg(&g_Ixs[m * NN + x]);
        ull cp = pk2(c, c), sp = pk2(s, s), sn = pk2(-s, -s);
        const ull* orp = reinterpret_cast<const ull*>(&sOF[m * 40]);
        const ull* oip = reinterpret_cast<const ull*>(&sOF[m * 40 + 20]);
#pragma unroll
        for (int q = 0; q < 10; q++) {
            ull o2 = orp[q], i2 = oip[q];
            fma2(Gr[q], o2, cp); fma2(Gr[q], i2, sn);
            fma2(Gi[q], o2, sp); fma2(Gi[q], i2, cp);
        }
    }
    float* dst = g_G + (((size_t)b * NN + x) * 64 + o) * 40;
#pragma unroll
    for (int q = 0; q < 10; q++) {
        float2 r = up2(Gr[q]), ii = up2(Gi[q]);
        dst[2 * q] = r.x; dst[2 * q + 1] = r.y;
        dst[20 + 2 * q] = ii.x; dst[20 + 2 * q + 1] = ii.y;
    }
}

// inv t-DFT + 1x1 conv + bias + exact GELU. Block = (x, t-half, b). 8o x 4t, f32x2 over o.
__global__ __launch_bounds__(272) void k_convinv(int sel, int layer,
                                                 const float* __restrict__ cb) {
    extern __shared__ float sm[];
    float* sH   = sm;                 // [64][136]
    float* sCWT = sH + 64 * 136;      // [64i][64o]
    float* sGT  = sCWT + 4096;        // [40n][68]
    float* sItc = sGT + 40 * 68;      // [20][136]
    float* sIts = sItc + 20 * 136;    // [20][136]
    const float* __restrict__ H  = sel ? g_H1 : g_H0;
    float* __restrict__       Hn = sel ? g_H0 : g_H1;
    int x = blockIdx.x, half = blockIdx.y, b = blockIdx.z;
    int tbase = half * 136;
    int tid = threadIdx.x;
    for (int idx = tid; idx < 64 * 136; idx += 272) {
        int i = idx / 136, tl = idx % 136;
        int t = tbase + tl;
        sH[idx] = (t < NN) ? H[(((size_t)b * 64 + i) * NN + x) * NN + t] : 0.f;
    }
    for (int idx = tid; idx < 4096; idx += 272)
        sCWT[idx] = g_cwT[layer * 4096 + idx];
    for (int idx = tid; idx < 2560; idx += 272) {
        int o = idx / 40, n = idx % 40;
        sGT[n * 68 + o] = g_G[((size_t)b * NN + x) * 2560 + idx];
    }
    for (int idx = tid; idx < 20 * 136; idx += 272) {
        int kt = idx / 136, tl = idx % 136;
        int t = tbase + tl;
        sItc[idx] = (t < NN) ? g_Itc[kt * NN + t] : 0.f;
        sIts[idx] = (t < NN) ? g_Its[kt * NN + t] : 0.f;
    }
    __syncthreads();
    int og = tid / 34, tq = tid % 34;
    int o0 = og * 8, t0 = tq * 4;
    ull acc[4][4] = {};                        // [o-pair][t]
#pragma unroll 2
    for (int i = 0; i < 64; i++) {
        float4 h4 = *(const float4*)&sH[i * 136 + t0];
        const ull* wp = reinterpret_cast<const ull*>(&sCWT[i * 64 + o0]);
        ull w0 = wp[0], w1 = wp[1], w2 = wp[2], w3 = wp[3];
        ull hp0 = pk2(h4.x, h4.x), hp1 = pk2(h4.y, h4.y);
        ull hp2 = pk2(h4.z, h4.z), hp3 = pk2(h4.w, h4.w);
        fma2(acc[0][0], w0, hp0); fma2(acc[0][1], w0, hp1);
        fma2(acc[0][2], w0, hp2); fma2(acc[0][3], w0, hp3);
        fma2(acc[1][0], w1, hp0); fma2(acc[1][1], w1, hp1);
        fma2(acc[1][2], w1, hp2); fma2(acc[1][3], w1, hp3);
        fma2(acc[2][0], w2, hp0); fma2(acc[2][1], w2, hp1);
        fma2(acc[2][2], w2, hp2); fma2(acc[2][3], w2, hp3);
        fma2(acc[3][0], w3, hp0); fma2(acc[3][1], w3, hp1);
        fma2(acc[3][2], w3, hp2); fma2(acc[3][3], w3, hp3);
    }
#pragma unroll
    for (int kt = 0; kt < 20; kt++) {
        float4 c4 = *(const float4*)&sItc[kt * 136 + t0];
        float4 s4 = *(const float4*)&sIts[kt * 136 + t0];
        const ull* gp = reinterpret_cast<const ull*>(&sGT[kt * 68 + o0]);
        const ull* ip = reinterpret_cast<const ull*>(&sGT[(20 + kt) * 68 + o0]);
        ull cc[4] = {pk2(c4.x, c4.x), pk2(c4.y, c4.y), pk2(c4.z, c4.z), pk2(c4.w, c4.w)};
        ull sn[4] = {pk2(-s4.x, -s4.x), pk2(-s4.y, -s4.y), pk2(-s4.z, -s4.z), pk2(-s4.w, -s4.w)};
#pragma unroll
        for (int p = 0; p < 4; p++) {
            ull gr = gp[p], gi = ip[p];
#pragma unroll
            for (int c = 0; c < 4; c++) {
                fma2(acc[p][c], gr, cc[c]);
                fma2(acc[p][c], gi, sn[c]);
            }
        }
    }
    int t0g = tbase + t0;
    if (t0g + 3 < NN) {
#pragma unroll
        for (int p = 0; p < 4; p++) {
            float2 v0 = up2(acc[p][0]), v1 = up2(acc[p][1]);
            float2 v2 = up2(acc[p][2]), v3 = up2(acc[p][3]);
            float ol[2][4] = {{v0.x, v1.x, v2.x, v3.x}, {v0.y, v1.y, v2.y, v3.y}};
#pragma unroll
            for (int h = 0; h < 2; h++) {
                int o = o0 + 2 * p + h;
                float cbv = __ldg(&cb[layer * 64 + o]);
                float4 out;
                float v;
                v = ol[h][0] + cbv; out.x = 0.5f * v * (1.f + erff(v * 0.7071067811865475f));
                v = ol[h][1] + cbv; out.y = 0.5f * v * (1.f + erff(v * 0.7071067811865475f));
                v = ol[h][2] + cbv; out.z = 0.5f * v * (1.f + erff(v * 0.7071067811865475f));
                v = ol[h][3] + cbv; out.w = 0.5f * v * (1.f + erff(v * 0.7071067811865475f));
                *(float4*)&Hn[(((size_t)b * 64 + o) * NN + x) * NN + t0g] = out;
            }
        }
    }
}

__global__ __launch_bounds__(256) void k_head(int sel, float* __restrict__ out) {
    const float* __restrict__ H = sel ? g_H1 : g_H0;
    __shared__ float sv[72];
    int tid = threadIdx.x;
    if (tid < 65) sv[tid] = g_v[tid];
    __syncthreads();
    int x = blockIdx.x, b = blockIdx.y;
    const float* base = H + ((size_t)b * 64 * NN + x) * NN + tid;
    float acc = sv[64];
#pragma unroll 8
    for (int c = 0; c < 64; c++) acc += base[(size_t)c * NSP] * sv[c];
    out[((size_t)b * 256 + x) * 256 + tid] = acc;
}

extern "C" void kernel_launch(void* const* d_in, const int* in_sizes, int n_in,
                              void* d_out, int out_size) {
    (void)in_sizes; (void)n_in; (void)out_size;
    const float* x    = (const float*)d_in[0];
    const float* wi_w = (const float*)d_in[1];
    const float* wi_b = (const float*)d_in[2];
    const float* w0_w = (const float*)d_in[3];
    const float* w0_b = (const float*)d_in[4];
    const float* sw1r = (const float*)d_in[5];
    const float* sw1i = (const float*)d_in[6];
    const float* sw2r = (const float*)d_in[7];
    const float* sw2i = (const float*)d_in[8];
    const float* cw   = (const float*)d_in[9];
    const float* cb   = (const float*)d_in[10];

    const int SM_CONV = (64 * 136 + 4096 + 40 * 68 + 2 * 20 * 136) * 4;  // 83840
    cudaFuncSetAttribute(k_convinv, cudaFuncAttributeMaxDynamicSharedMemorySize, SM_CONV);

    k_setup<<<212, 256>>>(cw, (const float*)d_in[11], (const float*)d_in[12],
                          (const float*)d_in[13], (const float*)d_in[14],
                          (const float*)d_in[15], (const float*)d_in[16]);
    k_liftQ<<<dim3(256, 8), 256>>>(x, wi_w, wi_b);
    k_expand<<<(512 * (NSP / 4) + 255) / 256, 256>>>(w0_w, w0_b);

    int sel = 0;
    for (int l = 0; l < 4; l++) {
        k_dftt<<<dim3(17, 512), 160>>>(sel);
        k_dftx<<<512, 800>>>();
        k_mix<<<dim3(40, 8), 640>>>(l, sw1r, sw1i, sw2r, sw2i);
        k_invx<<<dim3(64, 8), 268>>>();
        k_convinv<<<dim3(NN, 2, 8), 272, SM_CONV>>>(sel, l, cb);
        sel ^= 1;
    }
    k_head<<<dim3(256, 8), 256>>>(sel, (float*)d_out);
}

// round 8
// speedup vs baseline: 1.6134x; 1.1093x over previous
#include <cuda_runtime.h>
#include <math.h>

#define NN   268
#define NSP  71824
#define PI_D 3.141592653589793238462643383279502884

typedef unsigned long long ull;

static __device__ __align__(16) float g_H0[512 * NSP];
static __device__ __align__(16) float g_H1[512 * NSP];
static __device__ __align__(16) float g_F [512 * NN * 40];      // [bc][x][n] n<20 Re, n>=20 Im
static __device__ __align__(16) float g_Hf[8 * 40 * 64 * 40];   // [b][m][i][n]
static __device__ __align__(16) float g_OF[8 * 40 * 64 * 40];   // [b][m][o][n]
static __device__ __align__(16) float g_G [8 * NN * 64 * 40];   // [b][x][o][n]
static __device__ __align__(16) float g_Q [8 * 256 * 256];
static __device__ __align__(16) float g_Bt  [NN * 40];          // [t][n]
static __device__ __align__(16) float g_Exc [40 * NN];
static __device__ __align__(16) float g_Exs [40 * NN];
static __device__ __align__(16) float g_Ixc [40 * NN];
static __device__ __align__(16) float g_Ixs [40 * NN];
static __device__ __align__(16) float g_Itc [20 * NN];
static __device__ __align__(16) float g_Its [20 * NN];
static __device__ __align__(16) float g_cwT[4 * 64 * 64];       // [l][i][o]
static __device__ float g_v[72];

__device__ __forceinline__ ull pk2(float lo, float hi) {
    ull r; asm("mov.b64 %0, {%1,%2};" : "=l"(r) : "f"(lo), "f"(hi)); return r;
}
__device__ __forceinline__ void fma2(ull& d, ull a, ull b) {
    asm("fma.rn.f32x2 %0, %1, %2, %3;" : "=l"(d) : "l"(a), "l"(b), "l"(d));
}
__device__ __forceinline__ float2 up2(ull v) {
    float2 r; asm("mov.b64 {%0,%1}, %2;" : "=f"(r.x), "=f"(r.y) : "l"(v)); return r;
}

// merged setup: basis tables + cw transpose + collapsed fc head vector
__global__ void k_setup(const float* __restrict__ cw,
                        const float* __restrict__ f1w, const float* __restrict__ f1b,
                        const float* __restrict__ f2w, const float* __restrict__ f2b,
                        const float* __restrict__ f3w, const float* __restrict__ f3b) {
    int blk = blockIdx.x, tid = threadIdx.x;
    const double w = 2.0 * PI_D / 268.0;
    if (blk < 147) {
        int idx = blk * 256 + tid;
        if (idx < 10720) {                       // Bt[t][n]
            int t = idx / 40, n = idx % 40;
            int k = (n < 20) ? n : n - 20;
            double a = w * ((k * t) % 268);
            g_Bt[idx] = (n < 20) ? (float)cos(a) : (float)(-sin(a));
        } else if (idx < 21440) {                // Exc/Exs[m][x]
            int q = idx - 10720;
            int m = q / NN, x = q % NN;
            int kx = (m < 20) ? m : 228 + m;
            double a = w * ((kx * x) % 268);
            g_Exc[q] = (float)cos(a);
            g_Exs[q] = (float)(-sin(a));
        } else if (idx < 32160) {                // Ixc/Ixs[m][x], incl 1/N^2
            int q = idx - 21440;
            int m = q / NN, x = q % NN;
            int kx = (m < 20) ? m : 228 + m;
            double a = w * ((kx * x) % 268);
            double sc = 1.0 / (268.0 * 268.0);
            g_Ixc[q] = (float)(cos(a) * sc);
            g_Ixs[q] = (float)(sin(a) * sc);
        } else if (idx < 37520) {                // Itc/Its[k][t]
            int q = idx - 32160;
            int k = q / NN, t = q % NN;
            double a = w * ((k * t) % 268);
            double f = (k == 0) ? 1.0 : 2.0;
            g_Itc[q] = (float)(f * cos(a));
            g_Its[q] = (float)(f * sin(a));
        }
    } else if (blk < 211) {                      // cw transpose
        int idx = (blk - 147) * 256 + tid;
        if (idx < 16384) {
            int l = idx >> 12, r = idx & 4095, i = r >> 6, o = r & 63;
            g_cwT[idx] = cw[(l << 12) + (o << 6) + i];
        }
    } else {                                     // collapsed fc head
        if (tid < 64) {
            float acc = 0.f;
            for (int j = 0; j < 32; j++) {
                float s = 0.f;
                for (int r = 0; r < 128; r++) s += f2w[j * 128 + r] * f1w[r * 64 + tid];
                acc += f3w[j] * s;
            }
            g_v[tid] = acc;
        } else if (tid == 64) {
            float acc = f3b[0];
            for (int j = 0; j < 32; j++) {
                float s = f2b[j];
                for (int r = 0; r < 128; r++) s += f2w[j * 128 + r] * f1b[r];
                acc += f3w[j] * s;
            }
            g_v[64] = acc;
        }
    }
}

// Q[b][x][t] = sum_i X[b][i][t]*wiw[x][i] + wib[x]
__global__ __launch_bounds__(256) void k_liftQ(const float* __restrict__ X,
                                               const float* __restrict__ wiw,
                                               const float* __restrict__ wib) {
    int x = blockIdx.x, b = blockIdx.y, t = threadIdx.x;
    float acc = wib[x];
#pragma unroll
    for (int i = 0; i < 8; i++)
        acc += X[((size_t)b * 8 + i) * 256 + t] * wiw[x * 8 + i];
    g_Q[((size_t)b * 256 + x) * 256 + t] = acc;
}

// H0 padded 268x268: Q*w0w[c]+w0b[c] inside, 0 outside
__global__ __launch_bounds__(256) void k_expand(const float* __restrict__ w0w,
                                                const float* __restrict__ w0b) {
    int idx = blockIdx.x * 256 + threadIdx.x;
    if (idx >= 512 * (NSP / 4)) return;
    int p4 = idx % (NSP / 4), bc = idx / (NSP / 4);
    int c = bc & 63, b = bc >> 6;
    int p = p4 * 4, x = p / NN, t0 = p % NN;
    float4 v = make_float4(0.f, 0.f, 0.f, 0.f);
    if (x < 256 && t0 < 256) {
        float4 q = *(const float4*)&g_Q[((size_t)b * 256 + x) * 256 + t0];
        float wv = w0w[c], bb = w0b[c];
        v.x = q.x * wv + bb; v.y = q.y * wv + bb;
        v.z = q.z * wv + bb; v.w = q.w * wv + bb;
    }
    *(float4*)&g_H0[(size_t)bc * NSP + p] = v;
}

// F[bc][x][n] = sum_t H[bc][x][t]*Bt[t][n]
// 4 rows x 4 modes per thread, f32x2 accumulators. Block = 64 rows.
__global__ __launch_bounds__(160) void k_dftt(int sel) {
    const float* __restrict__ H = sel ? g_H1 : g_H0;
    extern __shared__ float sH[];                  // [64][268]
    int bc = blockIdx.y, x0 = blockIdx.x * 64, tid = threadIdx.x;
    for (int idx = tid; idx < 64 * NN; idx += 160) {
        int r = idx / NN, t = idx % NN;
        int x = x0 + r;
        sH[idx] = (x < NN) ? H[(size_t)bc * NSP + (size_t)x * NN + t] : 0.f;
    }
    __syncthreads();
    int tx = tid % 10, ty = tid / 10;              // tx: 4 modes, ty: 4 rows
    int r0 = ty * 4;
    ull a0l = 0, a0h = 0, a1l = 0, a1h = 0, a2l = 0, a2h = 0, a3l = 0, a3h = 0;
    const float* bp = g_Bt + tx * 4;
#pragma unroll 2
    for (int t = 0; t < NN; t++) {
        ulonglong2 b2 = __ldg(reinterpret_cast<const ulonglong2*>(bp + t * 40));
        float h0 = sH[(r0 + 0) * NN + t];
        float h1 = sH[(r0 + 1) * NN + t];
        float h2 = sH[(r0 + 2) * NN + t];
        float h3 = sH[(r0 + 3) * NN + t];
        ull p0 = pk2(h0, h0), p1 = pk2(h1, h1), p2 = pk2(h2, h2), p3 = pk2(h3, h3);
        fma2(a0l, b2.x, p0); fma2(a0h, b2.y, p0);
        fma2(a1l, b2.x, p1); fma2(a1h, b2.y, p1);
        fma2(a2l, b2.x, p2); fma2(a2h, b2.y, p2);
        fma2(a3l, b2.x, p3); fma2(a3h, b2.y, p3);
    }
    ull al[4] = {a0l, a1l, a2l, a3l};
    ull ah[4] = {a0h, a1h, a2h, a3h};
#pragma unroll
    for (int r = 0; r < 4; r++) {
        int x = x0 + r0 + r;
        if (x < NN) {
            float2 lo = up2(al[r]), hi = up2(ah[r]);
            *(float4*)&g_F[((size_t)bc * NN + x) * 40 + tx * 4] =
                make_float4(lo.x, lo.y, hi.x, hi.y);
        }
    }
}

// Hf[b][m][i][n] from F via 40-mode x-DFT. Thread = (m, 4 kt), f32x2.
__global__ __launch_bounds__(200) void k_dftx() {
    __shared__ float sF[NN * 40];
    int bc = blockIdx.x, tid = threadIdx.x;
    const float* src = g_F + (size_t)bc * NN * 40;
    for (int i = tid; i < NN * 40; i += 200) sF[i] = src[i];
    __syncthreads();
    int m = tid / 5, kt0 = (tid % 5) * 4;
    ull aR0 = 0, aR1 = 0, aI0 = 0, aI1 = 0;
    const float* ec = g_Exc + m * NN;
    const float* es = g_Exs + m * NN;
#pragma unroll 2
    for (int x = 0; x < NN; x++) {
        float c = __ldg(&ec[x]), s = __ldg(&es[x]);
        ull cp = pk2(c, c), sp = pk2(s, s), sn = pk2(-s, -s);
        const ull* f = reinterpret_cast<const ull*>(&sF[x * 40 + kt0]);
        const ull* g = reinterpret_cast<const ull*>(&sF[x * 40 + 20 + kt0]);
        ull fr0 = f[0], fr1 = f[1], fi0 = g[0], fi1 = g[1];
        fma2(aR0, fr0, cp); fma2(aR0, fi0, sn);
        fma2(aR1, fr1, cp); fma2(aR1, fi1, sn);
        fma2(aI0, fr0, sp); fma2(aI0, fi0, cp);
        fma2(aI1, fr1, sp); fma2(aI1, fi1, cp);
    }
    int b = bc >> 6, i = bc & 63;
    float* dst = g_Hf + (((size_t)b * 40 + m) * 64 + i) * 40;
    float2 r0 = up2(aR0), r1 = up2(aR1), i0 = up2(aI0), i1 = up2(aI1);
    *(float4*)&dst[kt0]      = make_float4(r0.x, r0.y, r1.x, r1.y);
    *(float4*)&dst[20 + kt0] = make_float4(i0.x, i0.y, i1.x, i1.y);
}

// OF[b][m][o][kt] = sum_i Hf[b][m][i][kt] * W[l][i][o][mm][kt]  (complex)
__global__ __launch_bounds__(640) void k_mix(int layer,
        const float* __restrict__ w1r, const float* __restrict__ w1i,
        const float* __restrict__ w2r, const float* __restrict__ w2i) {
    __shared__ float sH[2560];
    int m = blockIdx.x, b = blockIdx.y, tid = threadIdx.x;
    const float* src = g_Hf + ((size_t)b * 40 + m) * 2560;
    for (int i = tid; i < 2560; i += 640) sH[i] = src[i];
    __syncthreads();
    int kt = tid % 20, oh = tid / 20;
    const float* wr = (m < 20) ? w1r : w2r;
    const float* wi = (m < 20) ? w1i : w2i;
    int mm = (m < 20) ? m : m - 20;
    float aR0 = 0.f, aI0 = 0.f, aR1 = 0.f, aI1 = 0.f;
    for (int i = 0; i < 64; i++) {
        float hr = sH[i * 40 + kt], hi = sH[i * 40 + 20 + kt];
        size_t o0 = ((((size_t)layer * 64 + i) * 64 + oh) * 20 + mm) * 20 + kt;
        float w0r = __ldg(&wr[o0]),          w0i = __ldg(&wi[o0]);
        float w1rv = __ldg(&wr[o0 + 12800]), w1iv = __ldg(&wi[o0 + 12800]);
        aR0 += hr * w0r - hi * w0i;   aI0 += hr * w0i + hi * w0r;
        aR1 += hr * w1rv - hi * w1iv; aI1 += hr * w1iv + hi * w1rv;
    }
    float* d0 = g_OF + (((size_t)b * 40 + m) * 64 + oh) * 40;
    d0[kt] = aR0; d0[20 + kt] = aI0;
    d0[32 * 40 + kt] = aR1; d0[32 * 40 + 20 + kt] = aI1;
}

// G[b][x][o][n] = inverse x-DFT of OF  (f32x2, pairs over kt)
__global__ __launch_bounds__(268) void k_invx() {
    __shared__ float sOF[1600];
    int o = blockIdx.x, b = blockIdx.y, tid = threadIdx.x;
    for (int idx = tid; idx < 1600; idx += 268)
        sOF[idx] = g_OF[(((size_t)b * 40 + idx / 40) * 64 + o) * 40 + idx % 40];
    __syncthreads();
    int x = tid;
    ull Gr[10] = {}, Gi[10] = {};
    for (int m = 0; m < 40; m++) {
        float c = __ldg(&g_Ixc[m * NN + x]), s = __ldg(&g_Ixs[m * NN + x]);
        ull cp = pk2(c, c), sp = pk2(s, s), sn = pk2(-s, -s);
        const ull* orp = reinterpret_cast<const ull*>(&sOF[m * 40]);
        const ull* oip = reinterpret_cast<const ull*>(&sOF[m * 40 + 20]);
#pragma unroll
        for (int q = 0; q < 10; q++) {
            ull o2 = orp[q], i2 = oip[q];
            fma2(Gr[q], o2, cp); fma2(Gr[q], i2, sn);
            fma2(Gi[q], o2, sp); fma2(Gi[q], i2, cp);
        }
    }
    float* dst = g_G + (((size_t)b * NN + x) * 64 + o) * 40;
#pragma unroll
    for (int q = 0; q < 10; q++) {
        float2 r = up2(Gr[q]), ii = up2(Gi[q]);
        dst[2 * q] = r.x; dst[2 * q + 1] = r.y;
        dst[20 + 2 * q] = ii.x; dst[20 + 2 * q + 1] = ii.y;
    }
}

// inv t-DFT + 1x1 conv + bias + exact GELU. Block = (x, t-half, b). 8o x 4t, f32x2 over o.
__global__ __launch_bounds__(272) void k_convinv(int sel, int layer,
                                                 const float* __restrict__ cb) {
    extern __shared__ float sm[];
    float* sH   = sm;                 // [64][136]
    float* sCWT = sH + 64 * 136;      // [64i][64o]
    float* sGT  = sCWT + 4096;        // [40n][68]
    float* sItc = sGT + 40 * 68;      // [20][136]
    float* sIts = sItc + 20 * 136;    // [20][136]
    const float* __restrict__ H  = sel ? g_H1 : g_H0;
    float* __restrict__       Hn = sel ? g_H0 : g_H1;
    int x = blockIdx.x, half = blockIdx.y, b = blockIdx.z;
    int tbase = half * 136;
    int tid = threadIdx.x;
    for (int idx = tid; idx < 64 * 136; idx += 272) {
        int i = idx / 136, tl = idx % 136;
        int t = tbase + tl;
        sH[idx] = (t < NN) ? H[(((size_t)b * 64 + i) * NN + x) * NN + t] : 0.f;
    }
    for (int idx = tid; idx < 4096; idx += 272)
        sCWT[idx] = g_cwT[layer * 4096 + idx];
    for (int idx = tid; idx < 2560; idx += 272) {
        int o = idx / 40, n = idx % 40;
        sGT[n * 68 + o] = g_G[((size_t)b * NN + x) * 2560 + idx];
    }
    for (int idx = tid; idx < 20 * 136; idx += 272) {
        int kt = idx / 136, tl = idx % 136;
        int t = tbase + tl;
        sItc[idx] = (t < NN) ? g_Itc[kt * NN + t] : 0.f;
        sIts[idx] = (t < NN) ? g_Its[kt * NN + t] : 0.f;
    }
    __syncthreads();
    int og = tid / 34, tq = tid % 34;
    int o0 = og * 8, t0 = tq * 4;
    ull acc[4][4] = {};                        // [o-pair][t]
#pragma unroll 2
    for (int i = 0; i < 64; i++) {
        float4 h4 = *(const float4*)&sH[i * 136 + t0];
        const ull* wp = reinterpret_cast<const ull*>(&sCWT[i * 64 + o0]);
        ull w0 = wp[0], w1 = wp[1], w2 = wp[2], w3 = wp[3];
        ull hp0 = pk2(h4.x, h4.x), hp1 = pk2(h4.y, h4.y);
        ull hp2 = pk2(h4.z, h4.z), hp3 = pk2(h4.w, h4.w);
        fma2(acc[0][0], w0, hp0); fma2(acc[0][1], w0, hp1);
        fma2(acc[0][2], w0, hp2); fma2(acc[0][3], w0, hp3);
        fma2(acc[1][0], w1, hp0); fma2(acc[1][1], w1, hp1);
        fma2(acc[1][2], w1, hp2); fma2(acc[1][3], w1, hp3);
        fma2(acc[2][0], w2, hp0); fma2(acc[2][1], w2, hp1);
        fma2(acc[2][2], w2, hp2); fma2(acc[2][3], w2, hp3);
        fma2(acc[3][0], w3, hp0); fma2(acc[3][1], w3, hp1);
        fma2(acc[3][2], w3, hp2); fma2(acc[3][3], w3, hp3);
    }
#pragma unroll
    for (int kt = 0; kt < 20; kt++) {
        float4 c4 = *(const float4*)&sItc[kt * 136 + t0];
        float4 s4 = *(const float4*)&sIts[kt * 136 + t0];
        const ull* gp = reinterpret_cast<const ull*>(&sGT[kt * 68 + o0]);
        const ull* ip = reinterpret_cast<const ull*>(&sGT[(20 + kt) * 68 + o0]);
        ull cc[4] = {pk2(c4.x, c4.x), pk2(c4.y, c4.y), pk2(c4.z, c4.z), pk2(c4.w, c4.w)};
        ull sn[4] = {pk2(-s4.x, -s4.x), pk2(-s4.y, -s4.y), pk2(-s4.z, -s4.z), pk2(-s4.w, -s4.w)};
#pragma unroll
        for (int p = 0; p < 4; p++) {
            ull gr = gp[p], gi = ip[p];
#pragma unroll
            for (int c = 0; c < 4; c++) {
                fma2(acc[p][c], gr, cc[c]);
                fma2(acc[p][c], gi, sn[c]);
            }
        }
    }
    int t0g = tbase + t0;
    if (t0g + 3 < NN) {
#pragma unroll
        for (int p = 0; p < 4; p++) {
            float2 v0 = up2(acc[p][0]), v1 = up2(acc[p][1]);
            float2 v2 = up2(acc[p][2]), v3 = up2(acc[p][3]);
            float ol[2][4] = {{v0.x, v1.x, v2.x, v3.x}, {v0.y, v1.y, v2.y, v3.y}};
#pragma unroll
            for (int h = 0; h < 2; h++) {
                int o = o0 + 2 * p + h;
                float cbv = __ldg(&cb[layer * 64 + o]);
                float4 out;
                float v;
                v = ol[h][0] + cbv; out.x = 0.5f * v * (1.f + erff(v * 0.7071067811865475f));
                v = ol[h][1] + cbv; out.y = 0.5f * v * (1.f + erff(v * 0.7071067811865475f));
                v = ol[h][2] + cbv; out.z = 0.5f * v * (1.f + erff(v * 0.7071067811865475f));
                v = ol[h][3] + cbv; out.w = 0.5f * v * (1.f + erff(v * 0.7071067811865475f));
                *(float4*)&Hn[(((size_t)b * 64 + o) * NN + x) * NN + t0g] = out;
            }
        }
    }
}

__global__ __launch_bounds__(256) void k_head(int sel, float* __restrict__ out) {
    const float* __restrict__ H = sel ? g_H1 : g_H0;
    __shared__ float sv[72];
    int tid = threadIdx.x;
    if (tid < 65) sv[tid] = g_v[tid];
    __syncthreads();
    int x = blockIdx.x, b = blockIdx.y;
    const float* base = H + ((size_t)b * 64 * NN + x) * NN + tid;
    float acc = sv[64];
#pragma unroll 8
    for (int c = 0; c < 64; c++) acc += base[(size_t)c * NSP] * sv[c];
    out[((size_t)b * 256 + x) * 256 + tid] = acc;
}

extern "C" void kernel_launch(void* const* d_in, const int* in_sizes, int n_in,
                              void* d_out, int out_size) {
    (void)in_sizes; (void)n_in; (void)out_size;
    const float* x    = (const float*)d_in[0];
    const float* wi_w = (const float*)d_in[1];
    const float* wi_b = (const float*)d_in[2];
    const float* w0_w = (const float*)d_in[3];
    const float* w0_b = (const float*)d_in[4];
    const float* sw1r = (const float*)d_in[5];
    const float* sw1i = (const float*)d_in[6];
    const float* sw2r = (const float*)d_in[7];
    const float* sw2i = (const float*)d_in[8];
    const float* cw   = (const float*)d_in[9];
    const float* cb   = (const float*)d_in[10];

    const int SM_CONV = (64 * 136 + 4096 + 40 * 68 + 2 * 20 * 136) * 4;  // 83840
    const int SM_DFTT = 64 * NN * 4;                                     // 68608
    cudaFuncSetAttribute(k_convinv, cudaFuncAttributeMaxDynamicSharedMemorySize, SM_CONV);
    cudaFuncSetAttribute(k_dftt,    cudaFuncAttributeMaxDynamicSharedMemorySize, SM_DFTT);

    k_setup<<<212, 256>>>(cw, (const float*)d_in[11], (const float*)d_in[12],
                          (const float*)d_in[13], (const float*)d_in[14],
                          (const float*)d_in[15], (const float*)d_in[16]);
    k_liftQ<<<dim3(256, 8), 256>>>(x, wi_w, wi_b);
    k_expand<<<(512 * (NSP / 4) + 255) / 256, 256>>>(w0_w, w0_b);

    int sel = 0;
    for (int l = 0; l < 4; l++) {
        k_dftt<<<dim3(5, 512), 160, SM_DFTT>>>(sel);
        k_dftx<<<512, 200>>>();
        k_mix<<<dim3(40, 8), 640>>>(l, sw1r, sw1i, sw2r, sw2i);
        k_invx<<<dim3(64, 8), 268>>>();
        k_convinv<<<dim3(NN, 2, 8), 272, SM_CONV>>>(sel, l, cb);
        sel ^= 1;
    }
    k_head<<<dim3(256, 8), 256>>>(sel, (float*)d_out);
}

// round 10
// speedup vs baseline: 1.7132x; 1.0618x over previous
#include <cuda_runtime.h>
#include <math.h>

#define NN   268
#define NSP  71824
#define PI_D 3.141592653589793238462643383279502884

typedef unsigned long long ull;

static __device__ __align__(16) float g_H0[512 * NSP];
static __device__ __align__(16) float g_H1[512 * NSP];
static __device__ __align__(16) float g_F [512 * NN * 40];      // [bc][x][n] n<20 Re, n>=20 Im
static __device__ __align__(16) float g_Hf[8 * 40 * 64 * 40];   // [b][m][i][n]
static __device__ __align__(16) float g_OF[8 * 40 * 64 * 40];   // [b][m][o][n]
static __device__ __align__(16) float g_G [8 * NN * 64 * 40];   // [b][x][o][n]
static __device__ __align__(16) float g_Q [8 * 256 * 256];
static __device__ __align__(16) float g_Bt  [NN * 40];          // [t][n]
static __device__ __align__(16) float g_Exc [40 * NN];
static __device__ __align__(16) float g_Exs [40 * NN];
static __device__ __align__(16) float g_Ixc [40 * NN];
static __device__ __align__(16) float g_Ixs [40 * NN];
static __device__ __align__(16) float g_Itc [20 * NN];
static __device__ __align__(16) float g_Its [20 * NN];
static __device__ __align__(16) float g_cwT[4 * 64 * 64];       // [l][i][o]
static __device__ float g_v[72];

__device__ __forceinline__ ull pk2(float lo, float hi) {
    ull r; asm("mov.b64 %0, {%1,%2};" : "=l"(r) : "f"(lo), "f"(hi)); return r;
}
__device__ __forceinline__ void fma2(ull& d, ull a, ull b) {
    asm("fma.rn.f32x2 %0, %1, %2, %3;" : "=l"(d) : "l"(a), "l"(b), "l"(d));
}
__device__ __forceinline__ float2 up2(ull v) {
    float2 r; asm("mov.b64 {%0,%1}, %2;" : "=f"(r.x), "=f"(r.y) : "l"(v)); return r;
}

// merged setup: basis tables + cw transpose + collapsed fc head vector
__global__ void k_setup(const float* __restrict__ cw,
                        const float* __restrict__ f1w, const float* __restrict__ f1b,
                        const float* __restrict__ f2w, const float* __restrict__ f2b,
                        const float* __restrict__ f3w, const float* __restrict__ f3b) {
    int blk = blockIdx.x, tid = threadIdx.x;
    const double w = 2.0 * PI_D / 268.0;
    if (blk < 147) {
        int idx = blk * 256 + tid;
        if (idx < 10720) {                       // Bt[t][n]
            int t = idx / 40, n = idx % 40;
            int k = (n < 20) ? n : n - 20;
            double a = w * ((k * t) % 268);
            g_Bt[idx] = (n < 20) ? (float)cos(a) : (float)(-sin(a));
        } else if (idx < 21440) {                // Exc/Exs[m][x]
            int q = idx - 10720;
            int m = q / NN, x = q % NN;
            int kx = (m < 20) ? m : 228 + m;
            double a = w * ((kx * x) % 268);
            g_Exc[q] = (float)cos(a);
            g_Exs[q] = (float)(-sin(a));
        } else if (idx < 32160) {                // Ixc/Ixs[m][x], incl 1/N^2
            int q = idx - 21440;
            int m = q / NN, x = q % NN;
            int kx = (m < 20) ? m : 228 + m;
            double a = w * ((kx * x) % 268);
            double sc = 1.0 / (268.0 * 268.0);
            g_Ixc[q] = (float)(cos(a) * sc);
            g_Ixs[q] = (float)(sin(a) * sc);
        } else if (idx < 37520) {                // Itc/Its[k][t]
            int q = idx - 32160;
            int k = q / NN, t = q % NN;
            double a = w * ((k * t) % 268);
            double f = (k == 0) ? 1.0 : 2.0;
            g_Itc[q] = (float)(f * cos(a));
            g_Its[q] = (float)(f * sin(a));
        }
    } else if (blk < 211) {                      // cw transpose
        int idx = (blk - 147) * 256 + tid;
        if (idx < 16384) {
            int l = idx >> 12, r = idx & 4095, i = r >> 6, o = r & 63;
            g_cwT[idx] = cw[(l << 12) + (o << 6) + i];
        }
    } else {                                     // collapsed fc head
        if (tid < 64) {
            float acc = 0.f;
            for (int j = 0; j < 32; j++) {
                float s = 0.f;
                for (int r = 0; r < 128; r++) s += f2w[j * 128 + r] * f1w[r * 64 + tid];
                acc += f3w[j] * s;
            }
            g_v[tid] = acc;
        } else if (tid == 64) {
            float acc = f3b[0];
            for (int j = 0; j < 32; j++) {
                float s = f2b[j];
                for (int r = 0; r < 128; r++) s += f2w[j * 128 + r] * f1b[r];
                acc += f3w[j] * s;
            }
            g_v[64] = acc;
        }
    }
}

// Q[b][x][t] = sum_i X[b][i][t]*wiw[x][i] + wib[x]
__global__ __launch_bounds__(256) void k_liftQ(const float* __restrict__ X,
                                               const float* __restrict__ wiw,
                                               const float* __restrict__ wib) {
    int x = blockIdx.x, b = blockIdx.y, t = threadIdx.x;
    float acc = wib[x];
#pragma unroll
    for (int i = 0; i < 8; i++)
        acc += X[((size_t)b * 8 + i) * 256 + t] * wiw[x * 8 + i];
    g_Q[((size_t)b * 256 + x) * 256 + t] = acc;
}

// H0 padded 268x268: Q*w0w[c]+w0b[c] inside, 0 outside
__global__ __launch_bounds__(256) void k_expand(const float* __restrict__ w0w,
                                                const float* __restrict__ w0b) {
    int idx = blockIdx.x * 256 + threadIdx.x;
    if (idx >= 512 * (NSP / 4)) return;
    int p4 = idx % (NSP / 4), bc = idx / (NSP / 4);
    int c = bc & 63, b = bc >> 6;
    int p = p4 * 4, x = p / NN, t0 = p % NN;
    float4 v = make_float4(0.f, 0.f, 0.f, 0.f);
    if (x < 256 && t0 < 256) {
        float4 q = *(const float4*)&g_Q[((size_t)b * 256 + x) * 256 + t0];
        float wv = w0w[c], bb = w0b[c];
        v.x = q.x * wv + bb; v.y = q.y * wv + bb;
        v.z = q.z * wv + bb; v.w = q.w * wv + bb;
    }
    *(float4*)&g_H0[(size_t)bc * NSP + p] = v;
}

// F[bc][x][n] = sum_t H[bc][x][t]*Bt[t][n]
// 2 rows x 4 modes per thread, t unrolled x4 with LDS.128. Block = 64 rows, 320 thr.
__global__ __launch_bounds__(320) void k_dftt(int sel) {
    const float* __restrict__ H = sel ? g_H1 : g_H0;
    extern __shared__ float sH[];                  // [64][268]
    int bc = blockIdx.y, x0 = blockIdx.x * 64, tid = threadIdx.x;
    for (int idx = tid; idx < 64 * NN; idx += 320) {
        int r = idx / NN, t = idx - r * NN;
        int x = x0 + r;
        sH[idx] = (x < NN) ? H[(size_t)bc * NSP + (size_t)x * NN + t] : 0.f;
    }
    __syncthreads();
    int tx = tid % 10, ty = tid / 10;              // tx: 4 modes, ty: 2 rows
    int r0 = ty * 2;
    ull a0l = 0, a0h = 0, a1l = 0, a1h = 0;
    const float* bp = g_Bt + tx * 4;
    const float* row0 = sH + r0 * NN;
    const float* row1 = row0 + NN;
#pragma unroll 2
    for (int t = 0; t < NN; t += 4) {
        float4 h0 = *(const float4*)(row0 + t);
        float4 h1 = *(const float4*)(row1 + t);
        ulonglong2 b0 = __ldg(reinterpret_cast<const ulonglong2*>(bp + (t + 0) * 40));
        ulonglong2 b1 = __ldg(reinterpret_cast<const ulonglong2*>(bp + (t + 1) * 40));
        ulonglong2 b2 = __ldg(reinterpret_cast<const ulonglong2*>(bp + (t + 2) * 40));
        ulonglong2 b3 = __ldg(reinterpret_cast<const ulonglong2*>(bp + (t + 3) * 40));
        ull p;
        p = pk2(h0.x, h0.x); fma2(a0l, b0.x, p); fma2(a0h, b0.y, p);
        p = pk2(h0.y, h0.y); fma2(a0l, b1.x, p); fma2(a0h, b1.y, p);
        p = pk2(h0.z, h0.z); fma2(a0l, b2.x, p); fma2(a0h, b2.y, p);
        p = pk2(h0.w, h0.w); fma2(a0l, b3.x, p); fma2(a0h, b3.y, p);
        p = pk2(h1.x, h1.x); fma2(a1l, b0.x, p); fma2(a1h, b0.y, p);
        p = pk2(h1.y, h1.y); fma2(a1l, b1.x, p); fma2(a1h, b1.y, p);
        p = pk2(h1.z, h1.z); fma2(a1l, b2.x, p); fma2(a1h, b2.y, p);
        p = pk2(h1.w, h1.w); fma2(a1l, b3.x, p); fma2(a1h, b3.y, p);
    }
    int x = x0 + r0;
    if (x < NN) {
        float2 lo = up2(a0l), hi = up2(a0h);
        *(float4*)&g_F[((size_t)bc * NN + x) * 40 + tx * 4] =
            make_float4(lo.x, lo.y, hi.x, hi.y);
    }
    if (x + 1 < NN) {
        float2 lo = up2(a1l), hi = up2(a1h);
        *(float4*)&g_F[((size_t)bc * NN + x + 1) * 40 + tx * 4] =
            make_float4(lo.x, lo.y, hi.x, hi.y);
    }
}

// Hf[b][m][i][n] from F via 40-mode x-DFT. Thread = (m, 4 kt), f32x2.
__global__ __launch_bounds__(200) void k_dftx() {
    __shared__ float sF[NN * 40];
    int bc = blockIdx.x, tid = threadIdx.x;
    const float* src = g_F + (size_t)bc * NN * 40;
    for (int i = tid; i < NN * 40; i += 200) sF[i] = src[i];
    __syncthreads();
    int m = tid / 5, kt0 = (tid % 5) * 4;
    ull aR0 = 0, aR1 = 0, aI0 = 0, aI1 = 0;
    const float* ec = g_Exc + m * NN;
    const float* es = g_Exs + m * NN;
#pragma unroll 2
    for (int x = 0; x < NN; x++) {
        float c = __ldg(&ec[x]), s = __ldg(&es[x]);
        ull cp = pk2(c, c), sp = pk2(s, s), sn = pk2(-s, -s);
        const ull* f = reinterpret_cast<const ull*>(&sF[x * 40 + kt0]);
        const ull* g = reinterpret_cast<const ull*>(&sF[x * 40 + 20 + kt0]);
        ull fr0 = f[0], fr1 = f[1], fi0 = g[0], fi1 = g[1];
        fma2(aR0, fr0, cp); fma2(aR0, fi0, sn);
        fma2(aR1, fr1, cp); fma2(aR1, fi1, sn);
        fma2(aI0, fr0, sp); fma2(aI0, fi0, cp);
        fma2(aI1, fr1, sp); fma2(aI1, fi1, cp);
    }
    int b = bc >> 6, i = bc & 63;
    float* dst = g_Hf + (((size_t)b * 40 + m) * 64 + i) * 40;
    float2 r0 = up2(aR0), r1 = up2(aR1), i0 = up2(aI0), i1 = up2(aI1);
    *(float4*)&dst[kt0]      = make_float4(r0.x, r0.y, r1.x, r1.y);
    *(float4*)&dst[20 + kt0] = make_float4(i0.x, i0.y, i1.x, i1.y);
}

// OF[b][m][o][kt] = sum_i Hf[b][m][i][kt] * W[l][i][o][mm][kt]  (complex)
__global__ __launch_bounds__(640) void k_mix(int layer,
        const float* __restrict__ w1r, const float* __restrict__ w1i,
        const float* __restrict__ w2r, const float* __restrict__ w2i) {
    __shared__ float sH[2560];
    int m = blockIdx.x, b = blockIdx.y, tid = threadIdx.x;
    const float* src = g_Hf + ((size_t)b * 40 + m) * 2560;
    for (int i = tid; i < 2560; i += 640) sH[i] = src[i];
    __syncthreads();
    int kt = tid % 20, oh = tid / 20;
    const float* wr = (m < 20) ? w1r : w2r;
    const float* wi = (m < 20) ? w1i : w2i;
    int mm = (m < 20) ? m : m - 20;
    float aR0 = 0.f, aI0 = 0.f, aR1 = 0.f, aI1 = 0.f;
    for (int i = 0; i < 64; i++) {
        float hr = sH[i * 40 + kt], hi = sH[i * 40 + 20 + kt];
        size_t o0 = ((((size_t)layer * 64 + i) * 64 + oh) * 20 + mm) * 20 + kt;
        float w0r = __ldg(&wr[o0]),          w0i = __ldg(&wi[o0]);
        float w1rv = __ldg(&wr[o0 + 12800]), w1iv = __ldg(&wi[o0 + 12800]);
        aR0 += hr * w0r - hi * w0i;   aI0 += hr * w0i + hi * w0r;
        aR1 += hr * w1rv - hi * w1iv; aI1 += hr * w1iv + hi * w1rv;
    }
    float* d0 = g_OF + (((size_t)b * 40 + m) * 64 + oh) * 40;
    d0[kt] = aR0; d0[20 + kt] = aI0;
    d0[32 * 40 + kt] = aR1; d0[32 * 40 + 20 + kt] = aI1;
}

// G[b][x][o][n] = inverse x-DFT of OF  (f32x2, pairs over kt)
__global__ __launch_bounds__(268) void k_invx() {
    __shared__ float sOF[1600];
    int o = blockIdx.x, b = blockIdx.y, tid = threadIdx.x;
    for (int idx = tid; idx < 1600; idx += 268)
        sOF[idx] = g_OF[(((size_t)b * 40 + idx / 40) * 64 + o) * 40 + idx % 40];
    __syncthreads();
    int x = tid;
    ull Gr[10] = {}, Gi[10] = {};
    for (int m = 0; m < 40; m++) {
        float c = __ldg(&g_Ixc[m * NN + x]), s = __ldg(&g_Ixs[m * NN + x]);
        ull cp = pk2(c, c), sp = pk2(s, s), sn = pk2(-s, -s);
        const ull* orp = reinterpret_cast<const ull*>(&sOF[m * 40]);
        const ull* oip = reinterpret_cast<const ull*>(&sOF[m * 40 + 20]);
#pragma unroll
        for (int q = 0; q < 10; q++) {
            ull o2 = orp[q], i2 = oip[q];
            fma2(Gr[q], o2, cp); fma2(Gr[q], i2, sn);
            fma2(Gi[q], o2, sp); fma2(Gi[q], i2, cp);
        }
    }
    float* dst = g_G + (((size_t)b * NN + x) * 64 + o) * 40;
#pragma unroll
    for (int q = 0; q < 10; q++) {
        float2 r = up2(Gr[q]), ii = up2(Gi[q]);
        dst[2 * q] = r.x; dst[2 * q + 1] = r.y;
        dst[20 + 2 * q] = ii.x; dst[20 + 2 * q + 1] = ii.y;
    }
}

// inv t-DFT + 1x1 conv + bias + exact GELU. Block = (x, t-half, b). 8o x 2t, 544 thr.
__global__ __launch_bounds__(544) void k_convinv(int sel, int layer,
                                                 const float* __restrict__ cb) {
    extern __shared__ float sm[];
    float* sH   = sm;                 // [64][136]
    float* sCWT = sH + 64 * 136;      // [64i][64o]
    float* sGT  = sCWT + 4096;        // [40n][68]
    float* sItc = sGT + 40 * 68;      // [20][136]
    float* sIts = sItc + 20 * 136;    // [20][136]
    const float* __restrict__ H  = sel ? g_H1 : g_H0;
    float* __restrict__       Hn = sel ? g_H0 : g_H1;
    int x = blockIdx.x, half = blockIdx.y, b = blockIdx.z;
    int tbase = half * 136;
    int tid = threadIdx.x;
    for (int idx = tid; idx < 64 * 136; idx += 544) {
        int i = idx / 136, tl = idx % 136;
        int t = tbase + tl;
        sH[idx] = (t < NN) ? H[(((size_t)b * 64 + i) * NN + x) * NN + t] : 0.f;
    }
    for (int idx = tid; idx < 4096; idx += 544)
        sCWT[idx] = g_cwT[layer * 4096 + idx];
    for (int idx = tid; idx < 2560; idx += 544) {
        int o = idx / 40, n = idx % 40;
        sGT[n * 68 + o] = g_G[((size_t)b * NN + x) * 2560 + idx];
    }
    for (int idx = tid; idx < 20 * 136; idx += 544) {
        int kt = idx / 136, tl = idx % 136;
        int t = tbase + tl;
        sItc[idx] = (t < NN) ? g_Itc[kt * NN + t] : 0.f;
        sIts[idx] = (t < NN) ? g_Its[kt * NN + t] : 0.f;
    }
    __syncthreads();
    int og = tid / 68, tq = tid % 68;
    int o0 = og * 8, t0 = tq * 2;
    ull acc[4][2] = {};                        // [o-pair][t]
#pragma unroll 2
    for (int i = 0; i < 64; i++) {
        float2 h2 = *(const float2*)&sH[i * 136 + t0];
        const ull* wp = reinterpret_cast<const ull*>(&sCWT[i * 64 + o0]);
        ull w0 = wp[0], w1 = wp[1], w2 = wp[2], w3 = wp[3];
        ull hp0 = pk2(h2.x, h2.x), hp1 = pk2(h2.y, h2.y);
        fma2(acc[0][0], w0, hp0); fma2(acc[0][1], w0, hp1);
        fma2(acc[1][0], w1, hp0); fma2(acc[1][1], w1, hp1);
        fma2(acc[2][0], w2, hp0); fma2(acc[2][1], w2, hp1);
        fma2(acc[3][0], w3, hp0); fma2(acc[3][1], w3, hp1);
    }
#pragma unroll
    for (int kt = 0; kt < 20; kt++) {
        float2 c2 = *(const float2*)&sItc[kt * 136 + t0];
        float2 s2 = *(const float2*)&sIts[kt * 136 + t0];
        const ull* gp = reinterpret_cast<const ull*>(&sGT[kt * 68 + o0]);
        const ull* ip = reinterpret_cast<const ull*>(&sGT[(20 + kt) * 68 + o0]);
        ull cc0 = pk2(c2.x, c2.x), cc1 = pk2(c2.y, c2.y);
        ull sn0 = pk2(-s2.x, -s2.x), sn1 = pk2(-s2.y, -s2.y);
#pragma unroll
        for (int p = 0; p < 4; p++) {
            ull gr = gp[p], gi = ip[p];
            fma2(acc[p][0], gr, cc0); fma2(acc[p][0], gi, sn0);
            fma2(acc[p][1], gr, cc1); fma2(acc[p][1], gi, sn1);
        }
    }
    int t0g = tbase + t0;
    if (t0g + 1 < NN) {
#pragma unroll
        for (int p = 0; p < 4; p++) {
            float2 v0 = up2(acc[p][0]), v1 = up2(acc[p][1]);
            float ol[2][2] = {{v0.x, v1.x}, {v0.y, v1.y}};
#pragma unroll
            for (int h = 0; h < 2; h++) {
                int o = o0 + 2 * p + h;
                float cbv = __ldg(&cb[layer * 64 + o]);
                float2 out;
                float v;
                v = ol[h][0] + cbv; out.x = 0.5f * v * (1.f + erff(v * 0.7071067811865475f));
                v = ol[h][1] + cbv; out.y = 0.5f * v * (1.f + erff(v * 0.7071067811865475f));
                *(float2*)&Hn[(((size_t)b * 64 + o) * NN + x) * NN + t0g] = out;
            }
        }
    }
}

__global__ __launch_bounds__(256) void k_head(int sel, float* __restrict__ out) {
    const float* __restrict__ H = sel ? g_H1 : g_H0;
    __shared__ float sv[72];
    int tid = threadIdx.x;
    if (tid < 65) sv[tid] = g_v[tid];
    __syncthreads();
    int x = blockIdx.x, b = blockIdx.y;
    const float* base = H + ((size_t)b * 64 * NN + x) * NN + tid;
    float acc = sv[64];
#pragma unroll 8
    for (int c = 0; c < 64; c++) acc += base[(size_t)c * NSP] * sv[c];
    out[((size_t)b * 256 + x) * 256 + tid] = acc;
}

extern "C" void kernel_launch(void* const* d_in, const int* in_sizes, int n_in,
                              void* d_out, int out_size) {
    (void)in_sizes; (void)n_in; (void)out_size;
    const float* x    = (const float*)d_in[0];
    const float* wi_w = (const float*)d_in[1];
    const float* wi_b = (const float*)d_in[2];
    const float* w0_w = (const float*)d_in[3];
    const float* w0_b = (const float*)d_in[4];
    const float* sw1r = (const float*)d_in[5];
    const float* sw1i = (const float*)d_in[6];
    const float* sw2r = (const float*)d_in[7];
    const float* sw2i = (const float*)d_in[8];
    const float* cw   = (const float*)d_in[9];
    const float* cb   = (const float*)d_in[10];

    const int SM_CONV = (64 * 136 + 4096 + 40 * 68 + 2 * 20 * 136) * 4;  // 83840
    const int SM_DFTT = 64 * NN * 4;                                     // 68608
    cudaFuncSetAttribute(k_convinv, cudaFuncAttributeMaxDynamicSharedMemorySize, SM_CONV);
    cudaFuncSetAttribute(k_dftt,    cudaFuncAttributeMaxDynamicSharedMemorySize, SM_DFTT);

    k_setup<<<212, 256>>>(cw, (const float*)d_in[11], (const float*)d_in[12],
                          (const float*)d_in[13], (const float*)d_in[14],
                          (const float*)d_in[15], (const float*)d_in[16]);
    k_liftQ<<<dim3(256, 8), 256>>>(x, wi_w, wi_b);
    k_expand<<<(512 * (NSP / 4) + 255) / 256, 256>>>(w0_w, w0_b);

    int sel = 0;
    for (int l = 0; l < 4; l++) {
        k_dftt<<<dim3(5, 512), 320, SM_DFTT>>>(sel);
        k_dftx<<<512, 200>>>();
        k_mix<<<dim3(40, 8), 640>>>(l, sw1r, sw1i, sw2r, sw2i);
        k_invx<<<dim3(64, 8), 268>>>();
        k_convinv<<<dim3(NN, 2, 8), 544, SM_CONV>>>(sel, l, cb);
        sel ^= 1;
    }
    k_head<<<dim3(256, 8), 256>>>(sel, (float*)d_out);
}